// round 6
// baseline (speedup 1.0000x reference)
#include <cuda_runtime.h>
#include <cuda_fp16.h>
#include <stdint.h>

#define VOCAB 100000
#define EMBED 64
#define KIDS  20
#define BROWS (1024 * 50)          // B*S output rows

// Wt in fp16, [V, E]: each vocab row = 64 halves = 128 B = ONE L2 line.
// 12.8 MB — L2-resident (126 MB L2).
__device__ __half g_Wt[VOCAB * EMBED];

// ---------------------------------------------------------------------------
// Kernel 1: transpose + downconvert  W[E,V] f32 -> Wt[V,E] f16
// Tile = 32 v x 64 e (full embed dim). Grid = V/32 = 3125, block = 256.
// Read:  64 e-rows x 128B, fully coalesced.
// Write: each Wt vocab row (128B) stored by one warp as contiguous half2s.
// ---------------------------------------------------------------------------
__global__ __launch_bounds__(256)
void transpose_W_kernel(const float* __restrict__ W) {
    __shared__ float tile[EMBED][33];          // [e][v], +1 pad
    const int v0 = blockIdx.x * 32;
    const int tx = threadIdx.x & 31;           // v within tile
    const int ty = threadIdx.x >> 5;           // 0..7

    // Read all 64 embed rows for this 32-v slab.
    #pragma unroll
    for (int j = 0; j < 8; j++) {
        tile[ty + 8 * j][tx] =
            W[(size_t)(ty + 8 * j) * VOCAB + (v0 + tx)];
    }
    __syncthreads();

    // Write: 32 vrows x 32 half2 = 1024 half2; warp = one full 128B vrow.
    __half2* WtH2 = reinterpret_cast<__half2*>(g_Wt);
    const int tid = threadIdx.x;
    #pragma unroll
    for (int r = 0; r < 4; r++) {
        const int idx  = tid + r * 256;
        const int vrow = idx >> 5;             // 0..31 (constant per warp)
        const int c    = idx & 31;             // half2 col 0..31
        const float2 f = make_float2(tile[2 * c][vrow], tile[2 * c + 1][vrow]);
        WtH2[(size_t)(v0 + vrow) * (EMBED / 2) + c] = __float22half2_rn(f);
    }
}

// ---------------------------------------------------------------------------
// Kernel 2: gather-reduce. 8 lanes per row (lane owns 8 embeds = 16B of the
// 128B row), 64 rows per 512-thread block. 20 independent LDG.128 per thread.
// fp32 accumulation.
// ---------------------------------------------------------------------------
#define ROWS_PER_BLOCK 64
#define THREADS 512

__global__ __launch_bounds__(THREADS)
void gather_reduce_kernel(const int* __restrict__ ids,
                          const float* __restrict__ bias,
                          float* __restrict__ out) {
    __shared__ int s_ids[ROWS_PER_BLOCK * KIDS];   // 1280 ints

    const int tid = threadIdx.x;
    const size_t block_id_base = (size_t)blockIdx.x * (ROWS_PER_BLOCK * KIDS);

    // Coalesced stage of this block's 1280 ids.
    #pragma unroll
    for (int i = tid; i < ROWS_PER_BLOCK * KIDS; i += THREADS) {
        s_ids[i] = __ldg(ids + block_id_base + i);
    }

    const int row_local = tid >> 3;     // 0..63
    const int lane      = tid & 7;      // 0..7, owns e in [8*lane, 8*lane+8)

    // Bias: 8 floats per lane, broadcast across rows (L1-resident).
    const float4 b0 = __ldg(reinterpret_cast<const float4*>(bias) + 2 * lane);
    const float4 b1 = __ldg(reinterpret_cast<const float4*>(bias) + 2 * lane + 1);
    float acc[8] = { b0.x, b0.y, b0.z, b0.w, b1.x, b1.y, b1.z, b1.w };

    __syncthreads();

    int id[KIDS];
    #pragma unroll
    for (int k = 0; k < KIDS; k++) id[k] = s_ids[row_local * KIDS + k];

    const float4* WtV = reinterpret_cast<const float4*>(g_Wt);  // 16B = 8 halves

    #pragma unroll
    for (int k = 0; k < KIDS; k++) {
        const float4 raw = __ldg(&WtV[(size_t)id[k] * 8 + lane]);
        const __half2* h = reinterpret_cast<const __half2*>(&raw);
        #pragma unroll
        for (int p = 0; p < 4; p++) {
            const float2 f = __half22float2(h[p]);
            acc[2 * p]     += f.x;
            acc[2 * p + 1] += f.y;
        }
    }

    // Output: lane writes 32B; warp's 4 rows = 512B contiguous.
    const size_t row = (size_t)blockIdx.x * ROWS_PER_BLOCK + row_local;
    float4* o = reinterpret_cast<float4*>(out + row * EMBED + lane * 8);
    o[0] = make_float4(acc[0], acc[1], acc[2], acc[3]);
    o[1] = make_float4(acc[4], acc[5], acc[6], acc[7]);
}

// ---------------------------------------------------------------------------
// Launch: inputs in metadata order: content_input (int32), W (f32), b (f32)
// ---------------------------------------------------------------------------
extern "C" void kernel_launch(void* const* d_in, const int* in_sizes, int n_in,
                              void* d_out, int out_size) {
    const int*   ids  = (const int*)  d_in[0];   // [B, S, K] int32
    const float* W    = (const float*)d_in[1];   // [E, V] f32
    const float* bias = (const float*)d_in[2];   // [E] f32
    float*       out  = (float*)d_out;           // [B, S, E] f32

    transpose_W_kernel<<<VOCAB / 32, 256>>>(W);  // 3125 blocks

    const int blocks = BROWS / ROWS_PER_BLOCK;   // 800
    gather_reduce_kernel<<<blocks, THREADS>>>(ids, bias, out);
}